// round 12
// baseline (speedup 1.0000x reference)
#include <cuda_runtime.h>
#include <math.h>

// Problem constants
#define NB    16384
#define INK   64
#define CC    4
#define TOTC  16777216LL      // NB*CC*256 complex elements

// smem layout (float2 units): addr(i,j) = (i>>2)*68 + (i&3)*16 + j
#define GST   68
#define PL2   272             // plane: 4 groups * 68
#define MST   1090            // 4 planes * 272 + 2
#define MPB   4               // matrices per 64-thread block (2 per warp)
#define EIDX(i,j) ((((i) >> 2) * GST) + (((i) & 3) << 4) + (j))

// Scratch for intermediate M (interleaved re,im), 128 MiB
__device__ float2 g_M[TOTC];

// ---------------------------------------------------------------------------
// Packed f32x2 helpers
// ---------------------------------------------------------------------------
__device__ __forceinline__ unsigned long long pk2(float lo, float hi) {
    unsigned long long r;
    asm("mov.b64 %0, {%1, %2};" : "=l"(r) : "f"(lo), "f"(hi));
    return r;
}
__device__ __forceinline__ void upk2(unsigned long long v, float& lo, float& hi) {
    asm("mov.b64 {%0, %1}, %2;" : "=f"(lo), "=f"(hi) : "l"(v));
}
__device__ __forceinline__ unsigned long long ffma2(unsigned long long a,
                                                    unsigned long long b,
                                                    unsigned long long c) {
    unsigned long long r;
    asm("fma.rn.f32x2 %0, %1, %2, %3;" : "=l"(r) : "l"(a), "l"(b), "l"(c));
    return r;
}

// ---------------------------------------------------------------------------
// Kernel 1: M[n,c,i,j] -> g_M. One block: 16 n-values, one channel c; 256 thr.
// ---------------------------------------------------------------------------
__global__ __launch_bounds__(256) void ax_kernel(const float* __restrict__ dX,
                                                 const float* __restrict__ Ar,
                                                 const float* __restrict__ Ai,
                                                 int nDX, int nA) {
    __shared__ __align__(16) float2 dxs2[16][64];   // 8 KB, (d,d) duplicated
    int tid = threadIdx.x;
    int c   = blockIdx.x & 3;
    int n0  = (blockIdx.x >> 2) << 4;

    for (int idx = tid; idx < 1024; idx += 256) {
        int g = n0 * 64 + idx;
        float d = (g < nDX) ? dX[g] : 0.f;
        dxs2[idx >> 6][idx & 63] = make_float2(d, d);
    }
    __syncthreads();

    unsigned long long acc[16];
#pragma unroll
    for (int r = 0; r < 16; r++) acc[r] = 0ULL;

#pragma unroll 4
    for (int k = 0; k < 64; k += 2) {
        int gi0 = (((k    ) * 4 + c) << 8) + tid;
        int gi1 = (((k + 1) * 4 + c) << 8) + tid;
        float ar0 = (gi0 < nA) ? Ar[gi0] : 0.f;
        float ai0 = (gi0 < nA) ? Ai[gi0] : 0.f;
        float ar1 = (gi1 < nA) ? Ar[gi1] : 0.f;
        float ai1 = (gi1 < nA) ? Ai[gi1] : 0.f;
        unsigned long long ab0 = pk2(ar0, ai0);
        unsigned long long ab1 = pk2(ar1, ai1);
#pragma unroll
        for (int r = 0; r < 16; r++) {
            ulonglong2 d2 = *(const ulonglong2*)&dxs2[r][k];
            acc[r] = ffma2(d2.x, ab0, acc[r]);
            acc[r] = ffma2(d2.y, ab1, acc[r]);
        }
    }
#pragma unroll
    for (int r = 0; r < 16; r++) {
        long long o = ((long long)((n0 + r) * 4 + c)) * 256 + tid;
        float re, im;
        upk2(acc[r], re, im);
        g_M[o] = make_float2(re, im);
    }
}

// ---------------------------------------------------------------------------
// complex 16x16 matmul, 4x4 per-thread tile: rows r0..r0+3, cols j0..j0+3.
// ---------------------------------------------------------------------------
__device__ __forceinline__ void mm16_44(const float2* __restrict__ A,
                                        const float2* __restrict__ B,
                                        float2 c[4][4], int rg68, int j0) {
    unsigned long long accP[4][4], accQ[4][4];
#pragma unroll
    for (int r = 0; r < 4; r++)
#pragma unroll
        for (int l = 0; l < 4; l++) { accP[r][l] = 0ULL; accQ[r][l] = 0ULL; }
#pragma unroll
    for (int k = 0; k < 16; k++) {
        unsigned long long ar[4], ai[4];
#pragma unroll
        for (int r = 0; r < 4; r++) {
            float2 a = A[rg68 + (r << 4) + k];
            ar[r] = pk2(a.x, a.x);
            ai[r] = pk2(a.y, a.y);
        }
        ulonglong2 b01 = *(const ulonglong2*)(B + EIDX(k, j0));
        ulonglong2 b23 = *(const ulonglong2*)(B + EIDX(k, j0) + 2);
#pragma unroll
        for (int r = 0; r < 4; r++) {
            accP[r][0] = ffma2(ar[r], b01.x, accP[r][0]);  accQ[r][0] = ffma2(ai[r], b01.x, accQ[r][0]);
            accP[r][1] = ffma2(ar[r], b01.y, accP[r][1]);  accQ[r][1] = ffma2(ai[r], b01.y, accQ[r][1]);
            accP[r][2] = ffma2(ar[r], b23.x, accP[r][2]);  accQ[r][2] = ffma2(ai[r], b23.x, accQ[r][2]);
            accP[r][3] = ffma2(ar[r], b23.y, accP[r][3]);  accQ[r][3] = ffma2(ai[r], b23.y, accQ[r][3]);
        }
    }
#pragma unroll
    for (int r = 0; r < 4; r++)
#pragma unroll
        for (int l = 0; l < 4; l++) {
            float pr, pi2, qr, qi;
            upk2(accP[r][l], pr, pi2);
            upk2(accQ[r][l], qr, qi);
            c[r][l] = make_float2(pr - qi, pi2 + qr);
        }
}

__device__ __forceinline__ void store44(float2* __restrict__ dst,
                                        const float2 c[4][4], int rg68, int j0) {
#pragma unroll
    for (int r = 0; r < 4; r++) {
        float4* p = (float4*)(dst + rg68 + (r << 4) + j0);
        p[0] = make_float4(c[r][0].x, c[r][0].y, c[r][1].x, c[r][1].y);
        p[1] = make_float4(c[r][2].x, c[r][2].y, c[r][3].x, c[r][3].y);
    }
}

// ---------------------------------------------------------------------------
// Kernel 2: expm of AX = 0.5*(M - M^H), degree-15 Taylor (PS) + squaring.
// HALF-WARP (16 lanes) PER MATRIX; 4 matrices per 64-thread block.
// NEW: powers A2/A3/A4 computed UNSCALED; s chosen from spectral-norm bound
// ||A||_2 <= ||A4||_1^(1/4) with theta=3 (valid: A normal); planes then scaled
// once by sigma^k. Fewer squarings than 1-norm/theta=2.
// ---------------------------------------------------------------------------
__global__ __launch_bounds__(64) void expm_kernel(float* __restrict__ out,
                                                  long long capF, int writeComplex) {
    __shared__ __align__(16) float2 sm[MPB * MST];

    int tid  = threadIdx.x;
    int mloc = tid >> 4;              // matrix slot in block: 0..3
    int l16  = tid & 15;
    int rg   = l16 >> 2;
    int r0   = rg << 2;
    int rg68 = rg * GST;
    int j0   = (l16 & 3) << 2;

    float2* Am = sm + mloc * MST;
    float2* A2 = Am + PL2;
    float2* A4 = Am + 2 * PL2;
    float2* Pp = Am + 3 * PL2;

    long long baseC = ((long long)blockIdx.x * MPB + mloc) * 256;

    // stage M tile (4 rows x 4 cols) into P plane
#pragma unroll
    for (int r = 0; r < 4; r++) {
        const float4* g = (const float4*)(g_M + baseC + (r0 + r) * 16 + j0);
        float4 v0 = g[0], v1 = g[1];
        float4* p = (float4*)(Pp + rg68 + (r << 4) + j0);
        p[0] = v0; p[1] = v1;
    }
    __syncwarp();

    // AX = 0.5*(M - M^H), UNSCALED, into Am
    {
        float2 c[4][4];
#pragma unroll
        for (int r = 0; r < 4; r++) {
            int i = r0 + r;
#pragma unroll
            for (int l = 0; l < 4; l++) {
                int j = j0 + l;
                float2 mij = Pp[EIDX(i, j)];
                float2 mji = Pp[EIDX(j, i)];
                c[r][l] = make_float2(0.5f * (mij.x - mji.x), 0.5f * (mij.y + mji.y));
            }
        }
        store44(Am, c, rg68, j0);
    }
    __syncwarp();

    float2 a3[4][4];            // A3 tile in registers (unscaled, then scaled)
    float cs[4];                // column abs-sums of A4 (for norm bound)
    {
        float2 c[4][4];
        mm16_44(Am, Am, c, rg68, j0); store44(A2, c, rg68, j0);     // A2
        __syncwarp();
        mm16_44(A2, Am, a3, rg68, j0);                              // A3 -> regs
        mm16_44(A2, A2, c, rg68, j0); store44(A4, c, rg68, j0);     // A4
        // per-column partial sums of |re|+|im| (>= |z|, <= sqrt2*|z|)
#pragma unroll
        for (int l = 0; l < 4; l++) {
            float s4 = 0.f;
#pragma unroll
            for (int r = 0; r < 4; r++)
                s4 += fabsf(c[r][l].x) + fabsf(c[r][l].y);
            cs[l] = s4;
        }
    }

    // reduce column sums over the 4 row-groups, then max over columns
#pragma unroll
    for (int off = 8; off >= 4; off >>= 1)
#pragma unroll
        for (int l = 0; l < 4; l++)
            cs[l] += __shfl_xor_sync(0xffffffffu, cs[l], off);
    float mx = fmaxf(fmaxf(cs[0], cs[1]), fmaxf(cs[2], cs[3]));
#pragma unroll
    for (int off = 2; off >= 1; off >>= 1)
        mx = fmaxf(mx, __shfl_xor_sync(0xffffffffu, mx, off));

    // ||A||_2 <= mx^(1/4); s = ceil(log2(||A||_2 / 3)), theta = 3
    float t = 0.25f * log2f(mx) - 1.5849625007211562f;   // log2(3)
    int s = (t > 0.f) ? (int)ceilf(t) : 0;
    if (s > 20) s = 20;
    float sg  = exp2f(-(float)s);
    float sg2 = sg * sg;
    float sg3 = sg2 * sg;
    float sg4 = sg2 * sg2;

    // scale planes once: A *= sg, A2 *= sg2, A3(regs) *= sg3, A4 *= sg4
    if (s > 0) {
#pragma unroll
        for (int r = 0; r < 4; r++) {
#pragma unroll
            for (int l = 0; l < 4; l++) {
                int e = EIDX(r0 + r, j0 + l);
                float2 a = Am[e];  Am[e] = make_float2(a.x * sg,  a.y * sg);
                float2 b = A2[e];  A2[e] = make_float2(b.x * sg2, b.y * sg2);
                float2 d = A4[e];  A4[e] = make_float2(d.x * sg4, d.y * sg4);
                a3[r][l] = make_float2(a3[r][l].x * sg3, a3[r][l].y * sg3);
            }
        }
    }
    __syncwarp();

    const float c2  = 0.5f;
    const float c3  = 1.6666666666666666e-01f;
    const float c4  = 4.1666666666666664e-02f;
    const float c5  = 8.3333333333333332e-03f;
    const float c6  = 1.3888888888888889e-03f;
    const float c7  = 1.9841269841269841e-04f;
    const float c8  = 2.4801587301587302e-05f;
    const float c9  = 2.7557319223985893e-06f;
    const float c10 = 2.7557319223985888e-07f;
    const float c11 = 2.5052108385441720e-08f;
    const float c12 = 2.0876756987868100e-09f;
    const float c13 = 1.6059043836821613e-10f;
    const float c14 = 1.1470745597729725e-11f;
    const float c15 = 7.6471637318198164e-13f;

    // P = c12 I + c13 A + c14 A2 + c15 A3
#pragma unroll
    for (int r = 0; r < 4; r++) {
        int i = r0 + r;
#pragma unroll
        for (int l = 0; l < 4; l++) {
            int e = EIDX(i, j0 + l);
            float2 a = Am[e], b2 = A2[e];
            float2 v;
            v.x = c13 * a.x + c14 * b2.x + c15 * a3[r][l].x;
            v.y = c13 * a.y + c14 * b2.y + c15 * a3[r][l].y;
            if (i == j0 + l) v.x += c12;
            Pp[e] = v;
        }
    }
    __syncwarp();

    // Horner x3: P = P*A4 + (h0 I + h1 A + h2 A2 + h3 A3), in-place, no syncs
    const float h0[3] = { c8, c4, 1.0f };
    const float h1[3] = { c9, c5, 1.0f };
    const float h2[3] = { c10, c6, c2 };
    const float h3[3] = { c11, c7, c3 };
#pragma unroll
    for (int stp = 0; stp < 3; stp++) {
        float2 c[4][4];
        mm16_44(Pp, A4, c, rg68, j0);
#pragma unroll
        for (int r = 0; r < 4; r++) {
            int i = r0 + r;
#pragma unroll
            for (int l = 0; l < 4; l++) {
                int e = EIDX(i, j0 + l);
                float2 a = Am[e], b2 = A2[e];
                float2 v = c[r][l];
                v.x += h1[stp] * a.x + h2[stp] * b2.x + h3[stp] * a3[r][l].x;
                v.y += h1[stp] * a.y + h2[stp] * b2.y + h3[stp] * a3[r][l].y;
                if (i == j0 + l) v.x += h0[stp];
                Pp[e] = v;
            }
        }
    }
    __syncwarp();

    // repeated squaring: loop to warp-max s; store/swap predicated per matrix
    int sMax = s;
    sMax = max(sMax, __shfl_xor_sync(0xffffffffu, sMax, 16));
    float2* pr = Pp;
    float2* tr = Am;            // Am dead after Horner
    for (int it = 0; it < sMax; it++) {
        float2 c[4][4];
        mm16_44(pr, pr, c, rg68, j0);
        if (it < s) store44(tr, c, rg68, j0);
        __syncwarp();
        if (it < s) { float2* sw = pr; pr = tr; tr = sw; }
    }

    // write result (real-only float32 confirmed; complex path kept as fallback)
    if (writeComplex) {
#pragma unroll
        for (int r = 0; r < 4; r++) {
            int i = r0 + r;
#pragma unroll
            for (int l = 0; l < 4; l++) {
                int j = j0 + l;
                long long f = 2 * (baseC + i * 16 + j);
                float2 v = pr[EIDX(i, j)];
                if (f + 1 < capF) { out[f] = v.x; out[f + 1] = v.y; }
            }
        }
    } else {
#pragma unroll
        for (int r = 0; r < 4; r++) {
            int i = r0 + r;
            long long e = baseC + i * 16 + j0;
            if (e + 3 < capF) {
                float2 v0 = pr[EIDX(i, j0)],     v1 = pr[EIDX(i, j0 + 1)];
                float2 v2 = pr[EIDX(i, j0 + 2)], v3 = pr[EIDX(i, j0 + 3)];
                *(float4*)(out + e) = make_float4(v0.x, v1.x, v2.x, v3.x);
            }
        }
    }
}

// ---------------------------------------------------------------------------
extern "C" void kernel_launch(void* const* d_in, const int* in_sizes, int n_in,
                              void* d_out, int out_size) {
    int ix_dX = -1;
    for (int i = 0; i < n_in; i++)
        if (in_sizes[i] == (int)(NB * INK) || in_sizes[i] == (int)(NB * INK * 4)) { ix_dX = i; break; }
    if (ix_dX < 0) ix_dX = 0;
    int ia[2] = {0, 0}; int na = 0;
    for (int i = 0; i < n_in && na < 2; i++)
        if (i != ix_dX) ia[na++] = i;

    const float* dX = (const float*)d_in[ix_dX];
    const float* Ar = (const float*)d_in[ia[0]];
    const float* Ai = (const float*)d_in[ia[1]];
    float* outf = (float*)d_out;

    int nDX = in_sizes[ix_dX];
    int nA  = in_sizes[ia[0]] < in_sizes[ia[1]] ? in_sizes[ia[0]] : in_sizes[ia[1]];

    long long capF = (long long)out_size;
    if (capF > 2LL * TOTC) capF = 2LL * TOTC;
    int writeComplex = (capF >= 2LL * TOTC) ? 1 : 0;

    ax_kernel<<<(NB / 16) * CC, 256>>>(dX, Ar, Ai, nDX, nA);            // 4096 blocks
    expm_kernel<<<NB * CC / MPB, 64>>>(outf, capF, writeComplex);       // 16384 blocks
}

// round 13
// speedup vs baseline: 1.0540x; 1.0540x over previous
#include <cuda_runtime.h>
#include <math.h>

// Problem constants
#define NB    16384
#define INK   64
#define CC    4
#define TOTC  16777216LL      // NB*CC*256 complex elements

// smem layout (float2 units): addr(i,j) = (i>>2)*68 + (i&3)*16 + j
#define GST   68
#define PL2   272             // plane: 4 groups * 68
#define MST   1362            // 5 planes * 272 + 2
#define MPB   4               // matrices per 64-thread block (2 per warp)
#define EIDX(i,j) ((((i) >> 2) * GST) + (((i) & 3) << 4) + (j))

// Scratch for intermediate M (interleaved re,im), 128 MiB
__device__ float2 g_M[TOTC];

// ---------------------------------------------------------------------------
// Packed f32x2 helpers
// ---------------------------------------------------------------------------
__device__ __forceinline__ unsigned long long pk2(float lo, float hi) {
    unsigned long long r;
    asm("mov.b64 %0, {%1, %2};" : "=l"(r) : "f"(lo), "f"(hi));
    return r;
}
__device__ __forceinline__ void upk2(unsigned long long v, float& lo, float& hi) {
    asm("mov.b64 {%0, %1}, %2;" : "=f"(lo), "=f"(hi) : "l"(v));
}
__device__ __forceinline__ unsigned long long ffma2(unsigned long long a,
                                                    unsigned long long b,
                                                    unsigned long long c) {
    unsigned long long r;
    asm("fma.rn.f32x2 %0, %1, %2, %3;" : "=l"(r) : "l"(a), "l"(b), "l"(c));
    return r;
}

// ---------------------------------------------------------------------------
// Kernel 1: M[n,c,i,j] -> g_M. One block: 16 n-values, one channel c; 256 thr.
// ---------------------------------------------------------------------------
__global__ __launch_bounds__(256) void ax_kernel(const float* __restrict__ dX,
                                                 const float* __restrict__ Ar,
                                                 const float* __restrict__ Ai,
                                                 int nDX, int nA) {
    __shared__ __align__(16) float2 dxs2[16][64];   // 8 KB, (d,d) duplicated
    int tid = threadIdx.x;
    int c   = blockIdx.x & 3;
    int n0  = (blockIdx.x >> 2) << 4;

    for (int idx = tid; idx < 1024; idx += 256) {
        int g = n0 * 64 + idx;
        float d = (g < nDX) ? dX[g] : 0.f;
        dxs2[idx >> 6][idx & 63] = make_float2(d, d);
    }
    __syncthreads();

    unsigned long long acc[16];
#pragma unroll
    for (int r = 0; r < 16; r++) acc[r] = 0ULL;

#pragma unroll 4
    for (int k = 0; k < 64; k += 2) {
        int gi0 = (((k    ) * 4 + c) << 8) + tid;
        int gi1 = (((k + 1) * 4 + c) << 8) + tid;
        float ar0 = (gi0 < nA) ? Ar[gi0] : 0.f;
        float ai0 = (gi0 < nA) ? Ai[gi0] : 0.f;
        float ar1 = (gi1 < nA) ? Ar[gi1] : 0.f;
        float ai1 = (gi1 < nA) ? Ai[gi1] : 0.f;
        unsigned long long ab0 = pk2(ar0, ai0);
        unsigned long long ab1 = pk2(ar1, ai1);
#pragma unroll
        for (int r = 0; r < 16; r++) {
            ulonglong2 d2 = *(const ulonglong2*)&dxs2[r][k];
            acc[r] = ffma2(d2.x, ab0, acc[r]);
            acc[r] = ffma2(d2.y, ab1, acc[r]);
        }
    }
#pragma unroll
    for (int r = 0; r < 16; r++) {
        long long o = ((long long)((n0 + r) * 4 + c)) * 256 + tid;
        float re, im;
        upk2(acc[r], re, im);
        g_M[o] = make_float2(re, im);
    }
}

// ---------------------------------------------------------------------------
// complex 16x16 matmul, 4x4 per-thread tile: rows r0..r0+3, cols j0..j0+3.
// Dual packed accumulators: cr = P.lo - Q.hi, ci = P.hi + Q.lo.
// ---------------------------------------------------------------------------
__device__ __forceinline__ void mm16_44(const float2* __restrict__ A,
                                        const float2* __restrict__ B,
                                        float2 c[4][4], int rg68, int j0) {
    unsigned long long accP[4][4], accQ[4][4];
#pragma unroll
    for (int r = 0; r < 4; r++)
#pragma unroll
        for (int l = 0; l < 4; l++) { accP[r][l] = 0ULL; accQ[r][l] = 0ULL; }
#pragma unroll
    for (int k = 0; k < 16; k++) {
        unsigned long long ar[4], ai[4];
#pragma unroll
        for (int r = 0; r < 4; r++) {
            float2 a = A[rg68 + (r << 4) + k];
            ar[r] = pk2(a.x, a.x);
            ai[r] = pk2(a.y, a.y);
        }
        ulonglong2 b01 = *(const ulonglong2*)(B + EIDX(k, j0));
        ulonglong2 b23 = *(const ulonglong2*)(B + EIDX(k, j0) + 2);
#pragma unroll
        for (int r = 0; r < 4; r++) {
            accP[r][0] = ffma2(ar[r], b01.x, accP[r][0]);  accQ[r][0] = ffma2(ai[r], b01.x, accQ[r][0]);
            accP[r][1] = ffma2(ar[r], b01.y, accP[r][1]);  accQ[r][1] = ffma2(ai[r], b01.y, accQ[r][1]);
            accP[r][2] = ffma2(ar[r], b23.x, accP[r][2]);  accQ[r][2] = ffma2(ai[r], b23.x, accQ[r][2]);
            accP[r][3] = ffma2(ar[r], b23.y, accP[r][3]);  accQ[r][3] = ffma2(ai[r], b23.y, accQ[r][3]);
        }
    }
#pragma unroll
    for (int r = 0; r < 4; r++)
#pragma unroll
        for (int l = 0; l < 4; l++) {
            float pr, pi2, qr, qi;
            upk2(accP[r][l], pr, pi2);
            upk2(accQ[r][l], qr, qi);
            c[r][l] = make_float2(pr - qi, pi2 + qr);
        }
}

__device__ __forceinline__ void store44(float2* __restrict__ dst,
                                        const float2 c[4][4], int rg68, int j0) {
#pragma unroll
    for (int r = 0; r < 4; r++) {
        float4* p = (float4*)(dst + rg68 + (r << 4) + j0);
        p[0] = make_float4(c[r][0].x, c[r][0].y, c[r][1].x, c[r][1].y);
        p[1] = make_float4(c[r][2].x, c[r][2].y, c[r][3].x, c[r][3].y);
    }
}

// ---------------------------------------------------------------------------
// Kernel 2: expm of AX = 0.5*(M - M^H), degree-15 Taylor (PS) + squaring.
// HALF-WARP (16 lanes) PER MATRIX; 4 matrices per 64-thread block.
// Planes per matrix: Am, A2, A4, A3, P. A3 in smem (element-wise reads only)
// to free registers; __launch_bounds__(64,5) -> 10 warps/SM.
// ---------------------------------------------------------------------------
__global__ __launch_bounds__(64, 5) void expm_kernel(float* __restrict__ out,
                                                     long long capF, int writeComplex) {
    __shared__ __align__(16) float2 sm[MPB * MST];

    int tid  = threadIdx.x;
    int mloc = tid >> 4;              // matrix slot in block: 0..3
    int l16  = tid & 15;
    int rg   = l16 >> 2;
    int r0   = rg << 2;
    int rg68 = rg * GST;
    int j0   = (l16 & 3) << 2;

    float2* Am = sm + mloc * MST;
    float2* A2 = Am + PL2;
    float2* A4 = Am + 2 * PL2;
    float2* A3 = Am + 3 * PL2;
    float2* Pp = Am + 4 * PL2;

    long long baseC = ((long long)blockIdx.x * MPB + mloc) * 256;

    // stage M tile (4 rows x 4 cols) into P plane
#pragma unroll
    for (int r = 0; r < 4; r++) {
        const float4* g = (const float4*)(g_M + baseC + (r0 + r) * 16 + j0);
        float4 v0 = g[0], v1 = g[1];
        float4* p = (float4*)(Pp + rg68 + (r << 4) + j0);
        p[0] = v0; p[1] = v1;
    }
    __syncwarp();

    // AX = 0.5*(M - M^H); per-column partial abs-sums
    float2 ax[4][4];
    float cs[4];
#pragma unroll
    for (int l = 0; l < 4; l++) cs[l] = 0.f;
#pragma unroll
    for (int r = 0; r < 4; r++) {
        int i = r0 + r;
#pragma unroll
        for (int l = 0; l < 4; l++) {
            int j = j0 + l;
            float2 mij = Pp[EIDX(i, j)];
            float2 mji = Pp[EIDX(j, i)];
            float xr = 0.5f * (mij.x - mji.x);
            float xi = 0.5f * (mij.y + mji.y);
            ax[r][l] = make_float2(xr, xi);
            cs[l] += sqrtf(xr * xr + xi * xi);
        }
    }
    // reduce column sums over the 4 row-groups (xor 4, 8 stays in half-warp)
#pragma unroll
    for (int off = 8; off >= 4; off >>= 1)
#pragma unroll
        for (int l = 0; l < 4; l++)
            cs[l] += __shfl_xor_sync(0xffffffffu, cs[l], off);
    float mx = fmaxf(fmaxf(cs[0], cs[1]), fmaxf(cs[2], cs[3]));
#pragma unroll
    for (int off = 2; off >= 1; off >>= 1)
        mx = fmaxf(mx, __shfl_xor_sync(0xffffffffu, mx, off));

    int s = 0;
    if (mx > 1.0f) s = (int)ceilf(log2f(mx));
    s -= 1;                     // theta = 2 for degree-15 Taylor: trunc ~ 3e-9
    if (s < 0) s = 0;
    if (s > 24) s = 24;
    float scale = exp2f(-(float)s);

    // scaled A
    {
        float2 c[4][4];
#pragma unroll
        for (int r = 0; r < 4; r++)
#pragma unroll
            for (int l = 0; l < 4; l++)
                c[r][l] = make_float2(ax[r][l].x * scale, ax[r][l].y * scale);
        store44(Am, c, rg68, j0);
    }
    __syncwarp();

    {
        float2 c[4][4];
        mm16_44(Am, Am, c, rg68, j0); store44(A2, c, rg68, j0);     // A2
        __syncwarp();
        mm16_44(A2, Am, c, rg68, j0); store44(A3, c, rg68, j0);     // A3 (element-wise reads only)
        mm16_44(A2, A2, c, rg68, j0); store44(A4, c, rg68, j0);     // A4
    }
    __syncwarp();

    const float c2  = 0.5f;
    const float c3  = 1.6666666666666666e-01f;
    const float c4  = 4.1666666666666664e-02f;
    const float c5  = 8.3333333333333332e-03f;
    const float c6  = 1.3888888888888889e-03f;
    const float c7  = 1.9841269841269841e-04f;
    const float c8  = 2.4801587301587302e-05f;
    const float c9  = 2.7557319223985893e-06f;
    const float c10 = 2.7557319223985888e-07f;
    const float c11 = 2.5052108385441720e-08f;
    const float c12 = 2.0876756987868100e-09f;
    const float c13 = 1.6059043836821613e-10f;
    const float c14 = 1.1470745597729725e-11f;
    const float c15 = 7.6471637318198164e-13f;

    // P = c12 I + c13 A + c14 A2 + c15 A3
#pragma unroll
    for (int r = 0; r < 4; r++) {
        int i = r0 + r;
#pragma unroll
        for (int l = 0; l < 4; l++) {
            int e = EIDX(i, j0 + l);
            float2 a = Am[e], b2 = A2[e], b3 = A3[e];
            float2 v;
            v.x = c13 * a.x + c14 * b2.x + c15 * b3.x;
            v.y = c13 * a.y + c14 * b2.y + c15 * b3.y;
            if (i == j0 + l) v.x += c12;
            Pp[e] = v;
        }
    }
    __syncwarp();

    // Horner x3: P = P*A4 + (h0 I + h1 A + h2 A2 + h3 A3), in-place, no syncs
    const float h0[3] = { c8, c4, 1.0f };
    const float h1[3] = { c9, c5, 1.0f };
    const float h2[3] = { c10, c6, c2 };
    const float h3[3] = { c11, c7, c3 };
#pragma unroll
    for (int stp = 0; stp < 3; stp++) {
        float2 c[4][4];
        mm16_44(Pp, A4, c, rg68, j0);
#pragma unroll
        for (int r = 0; r < 4; r++) {
            int i = r0 + r;
#pragma unroll
            for (int l = 0; l < 4; l++) {
                int e = EIDX(i, j0 + l);
                float2 a = Am[e], b2 = A2[e], b3 = A3[e];
                float2 v = c[r][l];
                v.x += h1[stp] * a.x + h2[stp] * b2.x + h3[stp] * b3.x;
                v.y += h1[stp] * a.y + h2[stp] * b2.y + h3[stp] * b3.y;
                if (i == j0 + l) v.x += h0[stp];
                Pp[e] = v;
            }
        }
    }
    __syncwarp();

    // repeated squaring: loop to warp-max s; store/swap predicated per matrix
    int sMax = s;
    sMax = max(sMax, __shfl_xor_sync(0xffffffffu, sMax, 16));
    float2* pr = Pp;
    float2* tr = Am;            // Am dead after Horner
    for (int it = 0; it < sMax; it++) {
        float2 c[4][4];
        mm16_44(pr, pr, c, rg68, j0);
        if (it < s) store44(tr, c, rg68, j0);
        __syncwarp();
        if (it < s) { float2* sw = pr; pr = tr; tr = sw; }
    }

    // write result (real-only float32 confirmed; complex path kept as fallback)
    if (writeComplex) {
#pragma unroll
        for (int r = 0; r < 4; r++) {
            int i = r0 + r;
#pragma unroll
            for (int l = 0; l < 4; l++) {
                int j = j0 + l;
                long long f = 2 * (baseC + i * 16 + j);
                float2 v = pr[EIDX(i, j)];
                if (f + 1 < capF) { out[f] = v.x; out[f + 1] = v.y; }
            }
        }
    } else {
#pragma unroll
        for (int r = 0; r < 4; r++) {
            int i = r0 + r;
            long long e = baseC + i * 16 + j0;
            if (e + 3 < capF) {
                float2 v0 = pr[EIDX(i, j0)],     v1 = pr[EIDX(i, j0 + 1)];
                float2 v2 = pr[EIDX(i, j0 + 2)], v3 = pr[EIDX(i, j0 + 3)];
                *(float4*)(out + e) = make_float4(v0.x, v1.x, v2.x, v3.x);
            }
        }
    }
}

// ---------------------------------------------------------------------------
extern "C" void kernel_launch(void* const* d_in, const int* in_sizes, int n_in,
                              void* d_out, int out_size) {
    int ix_dX = -1;
    for (int i = 0; i < n_in; i++)
        if (in_sizes[i] == (int)(NB * INK) || in_sizes[i] == (int)(NB * INK * 4)) { ix_dX = i; break; }
    if (ix_dX < 0) ix_dX = 0;
    int ia[2] = {0, 0}; int na = 0;
    for (int i = 0; i < n_in && na < 2; i++)
        if (i != ix_dX) ia[na++] = i;

    const float* dX = (const float*)d_in[ix_dX];
    const float* Ar = (const float*)d_in[ia[0]];
    const float* Ai = (const float*)d_in[ia[1]];
    float* outf = (float*)d_out;

    int nDX = in_sizes[ix_dX];
    int nA  = in_sizes[ia[0]] < in_sizes[ia[1]] ? in_sizes[ia[0]] : in_sizes[ia[1]];

    long long capF = (long long)out_size;
    if (capF > 2LL * TOTC) capF = 2LL * TOTC;
    int writeComplex = (capF >= 2LL * TOTC) ? 1 : 0;

    ax_kernel<<<(NB / 16) * CC, 256>>>(dX, Ar, Ai, nDX, nA);            // 4096 blocks
    expm_kernel<<<NB * CC / MPB, 64>>>(outf, capF, writeComplex);       // 16384 blocks
}

// round 14
// speedup vs baseline: 1.5016x; 1.4247x over previous
#include <cuda_runtime.h>
#include <math.h>

// Problem constants
#define NB    16384
#define INK   64
#define CC    4
#define TOTC  16777216LL      // NB*CC*256 complex elements

// smem layout (float2 units): addr(i,j) = (i>>2)*68 + (i&3)*16 + j
#define GST   68
#define PL2   272             // plane: 4 groups * 68
#define MST   1090            // 4 planes * 272 + 2
#define MPB   4               // matrices per 64-thread block (2 per warp)
#define EIDX(i,j) ((((i) >> 2) * GST) + (((i) & 3) << 4) + (j))

// Scratch for intermediate M (interleaved re,im), 128 MiB
__device__ float2 g_M[TOTC];

// ---------------------------------------------------------------------------
// Packed f32x2 helpers
// ---------------------------------------------------------------------------
__device__ __forceinline__ unsigned long long pk2(float lo, float hi) {
    unsigned long long r;
    asm("mov.b64 %0, {%1, %2};" : "=l"(r) : "f"(lo), "f"(hi));
    return r;
}
__device__ __forceinline__ void upk2(unsigned long long v, float& lo, float& hi) {
    asm("mov.b64 {%0, %1}, %2;" : "=f"(lo), "=f"(hi) : "l"(v));
}
__device__ __forceinline__ unsigned long long ffma2(unsigned long long a,
                                                    unsigned long long b,
                                                    unsigned long long c) {
    unsigned long long r;
    asm("fma.rn.f32x2 %0, %1, %2, %3;" : "=l"(r) : "l"(a), "l"(b), "l"(c));
    return r;
}

// ---------------------------------------------------------------------------
// Kernel 1: M[n,c,i,j] -> g_M. One block: 32 n-values, one channel c; 256 thr.
// (32 rows/block halves the Ar/Ai L2 re-read traffic vs 16 rows/block.)
// ---------------------------------------------------------------------------
__global__ __launch_bounds__(256) void ax_kernel(const float* __restrict__ dX,
                                                 const float* __restrict__ Ar,
                                                 const float* __restrict__ Ai,
                                                 int nDX, int nA) {
    __shared__ __align__(16) float2 dxs2[32][64];   // 16 KB, (d,d) duplicated
    int tid = threadIdx.x;
    int c   = blockIdx.x & 3;
    int n0  = (blockIdx.x >> 2) << 5;

    for (int idx = tid; idx < 2048; idx += 256) {
        int g = n0 * 64 + idx;
        float d = (g < nDX) ? dX[g] : 0.f;
        dxs2[idx >> 6][idx & 63] = make_float2(d, d);
    }
    __syncthreads();

    unsigned long long acc[32];
#pragma unroll
    for (int r = 0; r < 32; r++) acc[r] = 0ULL;

#pragma unroll 2
    for (int k = 0; k < 64; k += 2) {
        int gi0 = (((k    ) * 4 + c) << 8) + tid;
        int gi1 = (((k + 1) * 4 + c) << 8) + tid;
        float ar0 = (gi0 < nA) ? Ar[gi0] : 0.f;
        float ai0 = (gi0 < nA) ? Ai[gi0] : 0.f;
        float ar1 = (gi1 < nA) ? Ar[gi1] : 0.f;
        float ai1 = (gi1 < nA) ? Ai[gi1] : 0.f;
        unsigned long long ab0 = pk2(ar0, ai0);
        unsigned long long ab1 = pk2(ar1, ai1);
#pragma unroll
        for (int r = 0; r < 32; r++) {
            ulonglong2 d2 = *(const ulonglong2*)&dxs2[r][k];
            acc[r] = ffma2(d2.x, ab0, acc[r]);
            acc[r] = ffma2(d2.y, ab1, acc[r]);
        }
    }
#pragma unroll
    for (int r = 0; r < 32; r++) {
        long long o = ((long long)((n0 + r) * 4 + c)) * 256 + tid;
        float re, im;
        upk2(acc[r], re, im);
        g_M[o] = make_float2(re, im);
    }
}

// ---------------------------------------------------------------------------
// complex 16x16 matmul, 4x4 per-thread tile: rows r0..r0+3, cols j0..j0+3.
// Dual packed accumulators: cr = P.lo - Q.hi, ci = P.hi + Q.lo.
// ---------------------------------------------------------------------------
__device__ __forceinline__ void mm16_44(const float2* __restrict__ A,
                                        const float2* __restrict__ B,
                                        float2 c[4][4], int rg68, int j0) {
    unsigned long long accP[4][4], accQ[4][4];
#pragma unroll
    for (int r = 0; r < 4; r++)
#pragma unroll
        for (int l = 0; l < 4; l++) { accP[r][l] = 0ULL; accQ[r][l] = 0ULL; }
#pragma unroll
    for (int k = 0; k < 16; k++) {
        unsigned long long ar[4], ai[4];
#pragma unroll
        for (int r = 0; r < 4; r++) {
            float2 a = A[rg68 + (r << 4) + k];
            ar[r] = pk2(a.x, a.x);
            ai[r] = pk2(a.y, a.y);
        }
        ulonglong2 b01 = *(const ulonglong2*)(B + EIDX(k, j0));
        ulonglong2 b23 = *(const ulonglong2*)(B + EIDX(k, j0) + 2);
#pragma unroll
        for (int r = 0; r < 4; r++) {
            accP[r][0] = ffma2(ar[r], b01.x, accP[r][0]);  accQ[r][0] = ffma2(ai[r], b01.x, accQ[r][0]);
            accP[r][1] = ffma2(ar[r], b01.y, accP[r][1]);  accQ[r][1] = ffma2(ai[r], b01.y, accQ[r][1]);
            accP[r][2] = ffma2(ar[r], b23.x, accP[r][2]);  accQ[r][2] = ffma2(ai[r], b23.x, accQ[r][2]);
            accP[r][3] = ffma2(ar[r], b23.y, accP[r][3]);  accQ[r][3] = ffma2(ai[r], b23.y, accQ[r][3]);
        }
    }
#pragma unroll
    for (int r = 0; r < 4; r++)
#pragma unroll
        for (int l = 0; l < 4; l++) {
            float pr, pi2, qr, qi;
            upk2(accP[r][l], pr, pi2);
            upk2(accQ[r][l], qr, qi);
            c[r][l] = make_float2(pr - qi, pi2 + qr);
        }
}

__device__ __forceinline__ void store44(float2* __restrict__ dst,
                                        const float2 c[4][4], int rg68, int j0) {
#pragma unroll
    for (int r = 0; r < 4; r++) {
        float4* p = (float4*)(dst + rg68 + (r << 4) + j0);
        p[0] = make_float4(c[r][0].x, c[r][0].y, c[r][1].x, c[r][1].y);
        p[1] = make_float4(c[r][2].x, c[r][2].y, c[r][3].x, c[r][3].y);
    }
}

// ---------------------------------------------------------------------------
// Kernel 2: expm of AX = 0.5*(M - M^H), degree-15 Taylor (PS) + squaring.
// HALF-WARP (16 lanes) PER MATRIX; 4 matrices per 64-thread block.
// Lane (within half): row group rg = l>>2 (rows 4rg..4rg+3), cols j0=(l&3)*4.
// Planes per matrix: Am, A2, A4, P (A3 lives in registers). [R11 structure]
// ---------------------------------------------------------------------------
__global__ __launch_bounds__(64) void expm_kernel(float* __restrict__ out,
                                                  long long capF, int writeComplex) {
    __shared__ __align__(16) float2 sm[MPB * MST];

    int tid  = threadIdx.x;
    int mloc = tid >> 4;              // matrix slot in block: 0..3
    int l16  = tid & 15;
    int rg   = l16 >> 2;
    int r0   = rg << 2;
    int rg68 = rg * GST;
    int j0   = (l16 & 3) << 2;

    float2* Am = sm + mloc * MST;
    float2* A2 = Am + PL2;
    float2* A4 = Am + 2 * PL2;
    float2* Pp = Am + 3 * PL2;

    long long baseC = ((long long)blockIdx.x * MPB + mloc) * 256;

    // stage M tile (4 rows x 4 cols) into P plane
#pragma unroll
    for (int r = 0; r < 4; r++) {
        const float4* g = (const float4*)(g_M + baseC + (r0 + r) * 16 + j0);
        float4 v0 = g[0], v1 = g[1];
        float4* p = (float4*)(Pp + rg68 + (r << 4) + j0);
        p[0] = v0; p[1] = v1;
    }
    __syncwarp();

    // AX = 0.5*(M - M^H); per-column partial abs-sums
    float2 ax[4][4];
    float cs[4];
#pragma unroll
    for (int l = 0; l < 4; l++) cs[l] = 0.f;
#pragma unroll
    for (int r = 0; r < 4; r++) {
        int i = r0 + r;
#pragma unroll
        for (int l = 0; l < 4; l++) {
            int j = j0 + l;
            float2 mij = Pp[EIDX(i, j)];
            float2 mji = Pp[EIDX(j, i)];
            float xr = 0.5f * (mij.x - mji.x);
            float xi = 0.5f * (mij.y + mji.y);
            ax[r][l] = make_float2(xr, xi);
            cs[l] += sqrtf(xr * xr + xi * xi);
        }
    }
    // reduce column sums over the 4 row-groups (xor 4, 8 stays in half-warp)
#pragma unroll
    for (int off = 8; off >= 4; off >>= 1)
#pragma unroll
        for (int l = 0; l < 4; l++)
            cs[l] += __shfl_xor_sync(0xffffffffu, cs[l], off);
    float mx = fmaxf(fmaxf(cs[0], cs[1]), fmaxf(cs[2], cs[3]));
#pragma unroll
    for (int off = 2; off >= 1; off >>= 1)
        mx = fmaxf(mx, __shfl_xor_sync(0xffffffffu, mx, off));

    // theta = 3: s = ceil(log2(||A||_1 / 3)); deg-15 trunc ~2.5e-6, amplified
    // ~2^s by squaring -> ~1e-4 worst case, well under the 1e-3 gate.
    float tt = log2f(mx) - 1.5849625007211562f;
    int s = (tt > 0.f) ? (int)ceilf(tt) : 0;
    if (s > 24) s = 24;
    float scale = exp2f(-(float)s);

    // scaled A
    {
        float2 c[4][4];
#pragma unroll
        for (int r = 0; r < 4; r++)
#pragma unroll
            for (int l = 0; l < 4; l++)
                c[r][l] = make_float2(ax[r][l].x * scale, ax[r][l].y * scale);
        store44(Am, c, rg68, j0);
    }
    __syncwarp();

    float2 a3[4][4];            // A3 tile in registers
    {
        float2 c[4][4];
        mm16_44(Am, Am, c, rg68, j0); store44(A2, c, rg68, j0);     // A2
        __syncwarp();
        mm16_44(A2, Am, a3, rg68, j0);                              // A3 -> regs
        mm16_44(A2, A2, c, rg68, j0); store44(A4, c, rg68, j0);     // A4
    }
    __syncwarp();

    const float c2  = 0.5f;
    const float c3  = 1.6666666666666666e-01f;
    const float c4  = 4.1666666666666664e-02f;
    const float c5  = 8.3333333333333332e-03f;
    const float c6  = 1.3888888888888889e-03f;
    const float c7  = 1.9841269841269841e-04f;
    const float c8  = 2.4801587301587302e-05f;
    const float c9  = 2.7557319223985893e-06f;
    const float c10 = 2.7557319223985888e-07f;
    const float c11 = 2.5052108385441720e-08f;
    const float c12 = 2.0876756987868100e-09f;
    const float c13 = 1.6059043836821613e-10f;
    const float c14 = 1.1470745597729725e-11f;
    const float c15 = 7.6471637318198164e-13f;

    // P = c12 I + c13 A + c14 A2 + c15 A3
#pragma unroll
    for (int r = 0; r < 4; r++) {
        int i = r0 + r;
#pragma unroll
        for (int l = 0; l < 4; l++) {
            int e = EIDX(i, j0 + l);
            float2 a = Am[e], b2 = A2[e];
            float2 v;
            v.x = c13 * a.x + c14 * b2.x + c15 * a3[r][l].x;
            v.y = c13 * a.y + c14 * b2.y + c15 * a3[r][l].y;
            if (i == j0 + l) v.x += c12;
            Pp[e] = v;
        }
    }
    __syncwarp();

    // Horner x3: P = P*A4 + (h0 I + h1 A + h2 A2 + h3 A3), in-place, no syncs
    const float h0[3] = { c8, c4, 1.0f };
    const float h1[3] = { c9, c5, 1.0f };
    const float h2[3] = { c10, c6, c2 };
    const float h3[3] = { c11, c7, c3 };
#pragma unroll
    for (int stp = 0; stp < 3; stp++) {
        float2 c[4][4];
        mm16_44(Pp, A4, c, rg68, j0);
#pragma unroll
        for (int r = 0; r < 4; r++) {
            int i = r0 + r;
#pragma unroll
            for (int l = 0; l < 4; l++) {
                int e = EIDX(i, j0 + l);
                float2 a = Am[e], b2 = A2[e];
                float2 v = c[r][l];
                v.x += h1[stp] * a.x + h2[stp] * b2.x + h3[stp] * a3[r][l].x;
                v.y += h1[stp] * a.y + h2[stp] * b2.y + h3[stp] * a3[r][l].y;
                if (i == j0 + l) v.x += h0[stp];
                Pp[e] = v;
            }
        }
    }
    __syncwarp();

    // repeated squaring: loop to warp-max s; store/swap predicated per matrix
    int sMax = s;
    sMax = max(sMax, __shfl_xor_sync(0xffffffffu, sMax, 16));
    float2* pr = Pp;
    float2* tr = Am;            // Am dead after Horner
    for (int it = 0; it < sMax; it++) {
        float2 c[4][4];
        mm16_44(pr, pr, c, rg68, j0);
        if (it < s) store44(tr, c, rg68, j0);
        __syncwarp();
        if (it < s) { float2* sw = pr; pr = tr; tr = sw; }
    }

    // write result (real-only float32 confirmed; complex path kept as fallback)
    if (writeComplex) {
#pragma unroll
        for (int r = 0; r < 4; r++) {
            int i = r0 + r;
#pragma unroll
            for (int l = 0; l < 4; l++) {
                int j = j0 + l;
                long long f = 2 * (baseC + i * 16 + j);
                float2 v = pr[EIDX(i, j)];
                if (f + 1 < capF) { out[f] = v.x; out[f + 1] = v.y; }
            }
        }
    } else {
#pragma unroll
        for (int r = 0; r < 4; r++) {
            int i = r0 + r;
            long long e = baseC + i * 16 + j0;
            if (e + 3 < capF) {
                float2 v0 = pr[EIDX(i, j0)],     v1 = pr[EIDX(i, j0 + 1)];
                float2 v2 = pr[EIDX(i, j0 + 2)], v3 = pr[EIDX(i, j0 + 3)];
                *(float4*)(out + e) = make_float4(v0.x, v1.x, v2.x, v3.x);
            }
        }
    }
}

// ---------------------------------------------------------------------------
extern "C" void kernel_launch(void* const* d_in, const int* in_sizes, int n_in,
                              void* d_out, int out_size) {
    int ix_dX = -1;
    for (int i = 0; i < n_in; i++)
        if (in_sizes[i] == (int)(NB * INK) || in_sizes[i] == (int)(NB * INK * 4)) { ix_dX = i; break; }
    if (ix_dX < 0) ix_dX = 0;
    int ia[2] = {0, 0}; int na = 0;
    for (int i = 0; i < n_in && na < 2; i++)
        if (i != ix_dX) ia[na++] = i;

    const float* dX = (const float*)d_in[ix_dX];
    const float* Ar = (const float*)d_in[ia[0]];
    const float* Ai = (const float*)d_in[ia[1]];
    float* outf = (float*)d_out;

    int nDX = in_sizes[ix_dX];
    int nA  = in_sizes[ia[0]] < in_sizes[ia[1]] ? in_sizes[ia[0]] : in_sizes[ia[1]];

    long long capF = (long long)out_size;
    if (capF > 2LL * TOTC) capF = 2LL * TOTC;
    int writeComplex = (capF >= 2LL * TOTC) ? 1 : 0;

    ax_kernel<<<(NB / 32) * CC, 256>>>(dX, Ar, Ai, nDX, nA);            // 2048 blocks
    expm_kernel<<<NB * CC / MPB, 64>>>(outf, capF, writeComplex);       // 16384 blocks
}

// round 15
// speedup vs baseline: 1.6474x; 1.0972x over previous
#include <cuda_runtime.h>
#include <math.h>

// Problem constants
#define NB    16384
#define INK   64
#define CC    4
#define TOTC  16777216LL      // NB*CC*256 complex elements

// smem layout (float2 units): addr(i,j) = (i>>2)*68 + (i&3)*16 + j
#define GST   68
#define PL2   272             // plane: 4 groups * 68
#define MST   1090            // 4 planes * 272 + 2
#define MPB   4               // matrices per 64-thread block (2 per warp)
#define EIDX(i,j) ((((i) >> 2) * GST) + (((i) & 3) << 4) + (j))

// Scratch for intermediate M (interleaved re,im), 128 MiB
__device__ float2 g_M[TOTC];

// ---------------------------------------------------------------------------
// Packed f32x2 helpers
// ---------------------------------------------------------------------------
__device__ __forceinline__ unsigned long long pk2(float lo, float hi) {
    unsigned long long r;
    asm("mov.b64 %0, {%1, %2};" : "=l"(r) : "f"(lo), "f"(hi));
    return r;
}
__device__ __forceinline__ void upk2(unsigned long long v, float& lo, float& hi) {
    asm("mov.b64 {%0, %1}, %2;" : "=f"(lo), "=f"(hi) : "l"(v));
}
__device__ __forceinline__ unsigned long long ffma2(unsigned long long a,
                                                    unsigned long long b,
                                                    unsigned long long c) {
    unsigned long long r;
    asm("fma.rn.f32x2 %0, %1, %2, %3;" : "=l"(r) : "l"(a), "l"(b), "l"(c));
    return r;
}

// ---------------------------------------------------------------------------
// Kernel 1: M[n,c,i,j] -> g_M. One block: 16 n-values, one channel c; 256 thr.
// (R11-validated version: 32 packed accumulators stays under the reg cliff.)
// ---------------------------------------------------------------------------
__global__ __launch_bounds__(256) void ax_kernel(const float* __restrict__ dX,
                                                 const float* __restrict__ Ar,
                                                 const float* __restrict__ Ai,
                                                 int nDX, int nA) {
    __shared__ __align__(16) float2 dxs2[16][64];   // 8 KB, (d,d) duplicated
    int tid = threadIdx.x;
    int c   = blockIdx.x & 3;
    int n0  = (blockIdx.x >> 2) << 4;

    for (int idx = tid; idx < 1024; idx += 256) {
        int g = n0 * 64 + idx;
        float d = (g < nDX) ? dX[g] : 0.f;
        dxs2[idx >> 6][idx & 63] = make_float2(d, d);
    }
    __syncthreads();

    unsigned long long acc[16];
#pragma unroll
    for (int r = 0; r < 16; r++) acc[r] = 0ULL;

#pragma unroll 4
    for (int k = 0; k < 64; k += 2) {
        int gi0 = (((k    ) * 4 + c) << 8) + tid;
        int gi1 = (((k + 1) * 4 + c) << 8) + tid;
        float ar0 = (gi0 < nA) ? Ar[gi0] : 0.f;
        float ai0 = (gi0 < nA) ? Ai[gi0] : 0.f;
        float ar1 = (gi1 < nA) ? Ar[gi1] : 0.f;
        float ai1 = (gi1 < nA) ? Ai[gi1] : 0.f;
        unsigned long long ab0 = pk2(ar0, ai0);
        unsigned long long ab1 = pk2(ar1, ai1);
#pragma unroll
        for (int r = 0; r < 16; r++) {
            ulonglong2 d2 = *(const ulonglong2*)&dxs2[r][k];
            acc[r] = ffma2(d2.x, ab0, acc[r]);
            acc[r] = ffma2(d2.y, ab1, acc[r]);
        }
    }
#pragma unroll
    for (int r = 0; r < 16; r++) {
        long long o = ((long long)((n0 + r) * 4 + c)) * 256 + tid;
        float re, im;
        upk2(acc[r], re, im);
        g_M[o] = make_float2(re, im);
    }
}

// ---------------------------------------------------------------------------
// complex 16x16 matmul, 4x4 per-thread tile: rows r0..r0+3, cols j0..j0+3.
// Dual packed accumulators: cr = P.lo - Q.hi, ci = P.hi + Q.lo.
// ---------------------------------------------------------------------------
__device__ __forceinline__ void mm16_44(const float2* __restrict__ A,
                                        const float2* __restrict__ B,
                                        float2 c[4][4], int rg68, int j0) {
    unsigned long long accP[4][4], accQ[4][4];
#pragma unroll
    for (int r = 0; r < 4; r++)
#pragma unroll
        for (int l = 0; l < 4; l++) { accP[r][l] = 0ULL; accQ[r][l] = 0ULL; }
#pragma unroll
    for (int k = 0; k < 16; k++) {
        unsigned long long ar[4], ai[4];
#pragma unroll
        for (int r = 0; r < 4; r++) {
            float2 a = A[rg68 + (r << 4) + k];
            ar[r] = pk2(a.x, a.x);
            ai[r] = pk2(a.y, a.y);
        }
        ulonglong2 b01 = *(const ulonglong2*)(B + EIDX(k, j0));
        ulonglong2 b23 = *(const ulonglong2*)(B + EIDX(k, j0) + 2);
#pragma unroll
        for (int r = 0; r < 4; r++) {
            accP[r][0] = ffma2(ar[r], b01.x, accP[r][0]);  accQ[r][0] = ffma2(ai[r], b01.x, accQ[r][0]);
            accP[r][1] = ffma2(ar[r], b01.y, accP[r][1]);  accQ[r][1] = ffma2(ai[r], b01.y, accQ[r][1]);
            accP[r][2] = ffma2(ar[r], b23.x, accP[r][2]);  accQ[r][2] = ffma2(ai[r], b23.x, accQ[r][2]);
            accP[r][3] = ffma2(ar[r], b23.y, accP[r][3]);  accQ[r][3] = ffma2(ai[r], b23.y, accQ[r][3]);
        }
    }
#pragma unroll
    for (int r = 0; r < 4; r++)
#pragma unroll
        for (int l = 0; l < 4; l++) {
            float pr, pi2, qr, qi;
            upk2(accP[r][l], pr, pi2);
            upk2(accQ[r][l], qr, qi);
            c[r][l] = make_float2(pr - qi, pi2 + qr);
        }
}

__device__ __forceinline__ void store44(float2* __restrict__ dst,
                                        const float2 c[4][4], int rg68, int j0) {
#pragma unroll
    for (int r = 0; r < 4; r++) {
        float4* p = (float4*)(dst + rg68 + (r << 4) + j0);
        p[0] = make_float4(c[r][0].x, c[r][0].y, c[r][1].x, c[r][1].y);
        p[1] = make_float4(c[r][2].x, c[r][2].y, c[r][3].x, c[r][3].y);
    }
}

// ---------------------------------------------------------------------------
// Kernel 2: expm of AX = 0.5*(M - M^H), degree-15 Taylor (PS) + squaring.
// HALF-WARP (16 lanes) PER MATRIX; 4 matrices per 64-thread block.
// Planes per matrix: Am, A2, A4, P (A3 lives in registers). theta=3 scaling.
// [R14-validated expm: 535 us]
// ---------------------------------------------------------------------------
__global__ __launch_bounds__(64) void expm_kernel(float* __restrict__ out,
                                                  long long capF, int writeComplex) {
    __shared__ __align__(16) float2 sm[MPB * MST];

    int tid  = threadIdx.x;
    int mloc = tid >> 4;              // matrix slot in block: 0..3
    int l16  = tid & 15;
    int rg   = l16 >> 2;
    int r0   = rg << 2;
    int rg68 = rg * GST;
    int j0   = (l16 & 3) << 2;

    float2* Am = sm + mloc * MST;
    float2* A2 = Am + PL2;
    float2* A4 = Am + 2 * PL2;
    float2* Pp = Am + 3 * PL2;

    long long baseC = ((long long)blockIdx.x * MPB + mloc) * 256;

    // stage M tile (4 rows x 4 cols) into P plane
#pragma unroll
    for (int r = 0; r < 4; r++) {
        const float4* g = (const float4*)(g_M + baseC + (r0 + r) * 16 + j0);
        float4 v0 = g[0], v1 = g[1];
        float4* p = (float4*)(Pp + rg68 + (r << 4) + j0);
        p[0] = v0; p[1] = v1;
    }
    __syncwarp();

    // AX = 0.5*(M - M^H); per-column partial abs-sums
    float2 ax[4][4];
    float cs[4];
#pragma unroll
    for (int l = 0; l < 4; l++) cs[l] = 0.f;
#pragma unroll
    for (int r = 0; r < 4; r++) {
        int i = r0 + r;
#pragma unroll
        for (int l = 0; l < 4; l++) {
            int j = j0 + l;
            float2 mij = Pp[EIDX(i, j)];
            float2 mji = Pp[EIDX(j, i)];
            float xr = 0.5f * (mij.x - mji.x);
            float xi = 0.5f * (mij.y + mji.y);
            ax[r][l] = make_float2(xr, xi);
            cs[l] += sqrtf(xr * xr + xi * xi);
        }
    }
    // reduce column sums over the 4 row-groups (xor 4, 8 stays in half-warp)
#pragma unroll
    for (int off = 8; off >= 4; off >>= 1)
#pragma unroll
        for (int l = 0; l < 4; l++)
            cs[l] += __shfl_xor_sync(0xffffffffu, cs[l], off);
    float mx = fmaxf(fmaxf(cs[0], cs[1]), fmaxf(cs[2], cs[3]));
#pragma unroll
    for (int off = 2; off >= 1; off >>= 1)
        mx = fmaxf(mx, __shfl_xor_sync(0xffffffffu, mx, off));

    // theta = 3: s = ceil(log2(||A||_1 / 3)); deg-15 trunc ~2.5e-6, amplified
    // ~2^s by squaring -> ~1e-4 worst case, well under the 1e-3 gate.
    float tt = log2f(mx) - 1.5849625007211562f;
    int s = (tt > 0.f) ? (int)ceilf(tt) : 0;
    if (s > 24) s = 24;
    float scale = exp2f(-(float)s);

    // scaled A
    {
        float2 c[4][4];
#pragma unroll
        for (int r = 0; r < 4; r++)
#pragma unroll
            for (int l = 0; l < 4; l++)
                c[r][l] = make_float2(ax[r][l].x * scale, ax[r][l].y * scale);
        store44(Am, c, rg68, j0);
    }
    __syncwarp();

    float2 a3[4][4];            // A3 tile in registers
    {
        float2 c[4][4];
        mm16_44(Am, Am, c, rg68, j0); store44(A2, c, rg68, j0);     // A2
        __syncwarp();
        mm16_44(A2, Am, a3, rg68, j0);                              // A3 -> regs
        mm16_44(A2, A2, c, rg68, j0); store44(A4, c, rg68, j0);     // A4
    }
    __syncwarp();

    const float c2  = 0.5f;
    const float c3  = 1.6666666666666666e-01f;
    const float c4  = 4.1666666666666664e-02f;
    const float c5  = 8.3333333333333332e-03f;
    const float c6  = 1.3888888888888889e-03f;
    const float c7  = 1.9841269841269841e-04f;
    const float c8  = 2.4801587301587302e-05f;
    const float c9  = 2.7557319223985893e-06f;
    const float c10 = 2.7557319223985888e-07f;
    const float c11 = 2.5052108385441720e-08f;
    const float c12 = 2.0876756987868100e-09f;
    const float c13 = 1.6059043836821613e-10f;
    const float c14 = 1.1470745597729725e-11f;
    const float c15 = 7.6471637318198164e-13f;

    // P = c12 I + c13 A + c14 A2 + c15 A3
#pragma unroll
    for (int r = 0; r < 4; r++) {
        int i = r0 + r;
#pragma unroll
        for (int l = 0; l < 4; l++) {
            int e = EIDX(i, j0 + l);
            float2 a = Am[e], b2 = A2[e];
            float2 v;
            v.x = c13 * a.x + c14 * b2.x + c15 * a3[r][l].x;
            v.y = c13 * a.y + c14 * b2.y + c15 * a3[r][l].y;
            if (i == j0 + l) v.x += c12;
            Pp[e] = v;
        }
    }
    __syncwarp();

    // Horner x3: P = P*A4 + (h0 I + h1 A + h2 A2 + h3 A3), in-place, no syncs
    const float h0[3] = { c8, c4, 1.0f };
    const float h1[3] = { c9, c5, 1.0f };
    const float h2[3] = { c10, c6, c2 };
    const float h3[3] = { c11, c7, c3 };
#pragma unroll
    for (int stp = 0; stp < 3; stp++) {
        float2 c[4][4];
        mm16_44(Pp, A4, c, rg68, j0);
#pragma unroll
        for (int r = 0; r < 4; r++) {
            int i = r0 + r;
#pragma unroll
            for (int l = 0; l < 4; l++) {
                int e = EIDX(i, j0 + l);
                float2 a = Am[e], b2 = A2[e];
                float2 v = c[r][l];
                v.x += h1[stp] * a.x + h2[stp] * b2.x + h3[stp] * a3[r][l].x;
                v.y += h1[stp] * a.y + h2[stp] * b2.y + h3[stp] * a3[r][l].y;
                if (i == j0 + l) v.x += h0[stp];
                Pp[e] = v;
            }
        }
    }
    __syncwarp();

    // repeated squaring: loop to warp-max s; store/swap predicated per matrix
    int sMax = s;
    sMax = max(sMax, __shfl_xor_sync(0xffffffffu, sMax, 16));
    float2* pr = Pp;
    float2* tr = Am;            // Am dead after Horner
    for (int it = 0; it < sMax; it++) {
        float2 c[4][4];
        mm16_44(pr, pr, c, rg68, j0);
        if (it < s) store44(tr, c, rg68, j0);
        __syncwarp();
        if (it < s) { float2* sw = pr; pr = tr; tr = sw; }
    }

    // write result (real-only float32 confirmed; complex path kept as fallback)
    if (writeComplex) {
#pragma unroll
        for (int r = 0; r < 4; r++) {
            int i = r0 + r;
#pragma unroll
            for (int l = 0; l < 4; l++) {
                int j = j0 + l;
                long long f = 2 * (baseC + i * 16 + j);
                float2 v = pr[EIDX(i, j)];
                if (f + 1 < capF) { out[f] = v.x; out[f + 1] = v.y; }
            }
        }
    } else {
#pragma unroll
        for (int r = 0; r < 4; r++) {
            int i = r0 + r;
            long long e = baseC + i * 16 + j0;
            if (e + 3 < capF) {
                float2 v0 = pr[EIDX(i, j0)],     v1 = pr[EIDX(i, j0 + 1)];
                float2 v2 = pr[EIDX(i, j0 + 2)], v3 = pr[EIDX(i, j0 + 3)];
                *(float4*)(out + e) = make_float4(v0.x, v1.x, v2.x, v3.x);
            }
        }
    }
}

// ---------------------------------------------------------------------------
extern "C" void kernel_launch(void* const* d_in, const int* in_sizes, int n_in,
                              void* d_out, int out_size) {
    int ix_dX = -1;
    for (int i = 0; i < n_in; i++)
        if (in_sizes[i] == (int)(NB * INK) || in_sizes[i] == (int)(NB * INK * 4)) { ix_dX = i; break; }
    if (ix_dX < 0) ix_dX = 0;
    int ia[2] = {0, 0}; int na = 0;
    for (int i = 0; i < n_in && na < 2; i++)
        if (i != ix_dX) ia[na++] = i;

    const float* dX = (const float*)d_in[ix_dX];
    const float* Ar = (const float*)d_in[ia[0]];
    const float* Ai = (const float*)d_in[ia[1]];
    float* outf = (float*)d_out;

    int nDX = in_sizes[ix_dX];
    int nA  = in_sizes[ia[0]] < in_sizes[ia[1]] ? in_sizes[ia[0]] : in_sizes[ia[1]];

    long long capF = (long long)out_size;
    if (capF > 2LL * TOTC) capF = 2LL * TOTC;
    int writeComplex = (capF >= 2LL * TOTC) ? 1 : 0;

    ax_kernel<<<(NB / 16) * CC, 256>>>(dX, Ar, Ai, nDX, nA);            // 4096 blocks
    expm_kernel<<<NB * CC / MPB, 64>>>(outf, capF, writeComplex);       // 16384 blocks
}